// round 6
// baseline (speedup 1.0000x reference)
#include <cuda_runtime.h>

#define Bn 32
#define Tn 128
#define In 256
#define Hn 256
#define IH 512
#define On 128
#define NBLK 256      // persistent blocks; 64 KB smem, <=128 regs => 2 blocks/SM
#define NTHR 256      // 8 warps

__device__ float g_h[2][Bn * Hn];   // ping-pong hidden state
__device__ unsigned g_bar;          // monotonic grid-barrier counter

// ---------------------------------------------------------------------------
__global__ void init_kernel()
{
    int i = blockIdx.x * blockDim.x + threadIdx.x;
    if (i == 0) g_bar = 0u;
    for (int k = i; k < Bn * Hn; k += gridDim.x * blockDim.x) g_h[0][k] = 0.f;
}

// ---------------------------------------------------------------------------
__device__ __forceinline__ float warp_sum(float v)
{
#pragma unroll
    for (int o = 16; o > 0; o >>= 1) v += __shfl_xor_sync(0xffffffffu, v, o);
    return v;
}
__device__ __forceinline__ float tanh_fast(float v)
{
    float r; asm("tanh.approx.f32 %0, %1;" : "=f"(r) : "f"(v)); return r;
}
__device__ __forceinline__ unsigned ld_acquire(const unsigned* p)
{
    unsigned v;
    asm volatile("ld.acquire.gpu.global.u32 %0, [%1];" : "=r"(v) : "l"(p) : "memory");
    return v;
}
__device__ __forceinline__ void red_release(unsigned* p)
{
    asm volatile("red.release.gpu.global.add.u32 [%0], 1;" :: "l"(p) : "memory");
}
__device__ __forceinline__ float d4(float4 a, float4 b)
{
    return a.x * b.x + a.y * b.y + a.z * b.z + a.w * b.w;
}

// ---------------------------------------------------------------------------
// Persistent kernel, 2 blocks/SM. Block owns h-row bid x 32 batches; F slice
// (32 rows x 512 = 64 KB) in smem. Warp w handles batches w + {0,8,16,24}.
// Lane f-slice: float4 idx k*32+lane, k=0..3.
//
// FUSED structure: the writeback of step t computes, from the F_new register
// values, the step-(t+1) partials ss=||W+F_new||^2 and dx=x(t+1)·(W+F_new).
// => F is read once and written once per step (was read 2x). The ss reduce +
// rsqrt run before the barrier wait (off the critical path).
// ---------------------------------------------------------------------------
__global__ __launch_bounds__(NTHR, 2) void persist_kernel(
    const float* __restrict__ x,
    const float* __restrict__ Wl,
    const float* __restrict__ Wg,
    const float* __restrict__ W,
    const float* __restrict__ bias,
    const float* __restrict__ Wout,
    const float* __restrict__ bout,
    float* __restrict__ out)
{
    extern __shared__ float F_sm[];            // 32 * 512 floats = 64 KB
    float4* __restrict__ F4 = (float4*)F_sm;   // [32][128]

    const int tid  = threadIdx.x;
    const int wid  = tid >> 5, lane = tid & 31;
    const int bi0  = wid;                      // 0..7
    const int h    = blockIdx.x;

    // Pin this block's weight-row slices in registers.
    float4 w4[4], l4[4], g4[4];
    {
        const float4* Wp = (const float4*)(W  + (size_t)h * IH);
        const float4* Lp = (const float4*)(Wl + (size_t)h * IH);
        const float4* Gp = (const float4*)(Wg + (size_t)h * IH);
#pragma unroll
        for (int k = 0; k < 4; k++) {
            int f4 = k * 32 + lane;
            w4[k] = __ldg(Wp + f4);
            l4[k] = __ldg(Lp + f4);
            g4[k] = __ldg(Gp + f4);
        }
    }
    const float bia = __ldg(bias + h);

    // Zero this warp's F rows (warp-private).
    {
        float4 z = make_float4(0.f, 0.f, 0.f, 0.f);
#pragma unroll
        for (int u = 0; u < 4; u++) {
            float4* Fr = F4 + (bi0 + u * 8) * (IH / 4);
#pragma unroll
            for (int k = 0; k < 4; k++) Fr[k * 32 + lane] = z;
        }
    }

    // Bootstrap partials for t=0 (F=0 => tw=W).
    float ssp[4], dxp[4], rn[4];
    {
        const float ssw = d4(w4[0], w4[0]) + d4(w4[1], w4[1])
                        + d4(w4[2], w4[2]) + d4(w4[3], w4[3]);
#pragma unroll
        for (int u = 0; u < 4; u++) {
            const int bi = bi0 + u * 8;
            const float4* xr = (const float4*)(x + (size_t)bi * Tn * In);
            float4 xv0 = __ldg(xr + lane);
            float4 xv1 = __ldg(xr + 32 + lane);
            ssp[u] = ssw;
            dxp[u] = d4(xv0, w4[0]) + d4(xv1, w4[1]);
        }
    }

    for (int t = 0; t < Tn; t++) {
        const float4* __restrict__ hin = (const float4*)g_h[t & 1];
        float* __restrict__ hout = g_h[(t & 1) ^ 1];
        const int tn = (t + 1 < Tn) ? t + 1 : t;   // clamped next-x index

        // ss reduce + rsqrt: barrier-independent, 4 interleaved chains.
#pragma unroll
        for (int o = 16; o > 0; o >>= 1) {
            ssp[0] += __shfl_xor_sync(0xffffffffu, ssp[0], o);
            ssp[1] += __shfl_xor_sync(0xffffffffu, ssp[1], o);
            ssp[2] += __shfl_xor_sync(0xffffffffu, ssp[2], o);
            ssp[3] += __shfl_xor_sync(0xffffffffu, ssp[3], o);
        }
#pragma unroll
        for (int u = 0; u < 4; u++) rn[u] = rsqrtf(ssp[u]);

        // ---------- wait: h(t-1) published by all blocks ----------
        if (tid == 0) {
            const unsigned target = (unsigned)NBLK * (unsigned)t;
            while (ld_acquire(&g_bar) < target) __nanosleep(32);
        }
        __syncthreads();

        // ---------- fused B: dot, tanh, writeback + next-step partials ----------
        float4 ha = __ldcg(hin + bi0 * (Hn / 4) + lane);
        float4 hb = __ldcg(hin + bi0 * (Hn / 4) + 32 + lane);
#pragma unroll
        for (int u = 0; u < 4; u++) {
            const int bi = bi0 + u * 8;
            float4 han, hbn;
            if (u < 3) {
                han = __ldcg(hin + (bi + 8) * (Hn / 4) + lane);
                hbn = __ldcg(hin + (bi + 8) * (Hn / 4) + 32 + lane);
            }
            float4* __restrict__ Fr = F4 + bi * (IH / 4);

            float4 Fv2 = Fr[64 + lane], Fv3 = Fr[96 + lane];
            float4 tw2, tw3;
            tw2.x = w4[2].x + Fv2.x; tw2.y = w4[2].y + Fv2.y; tw2.z = w4[2].z + Fv2.z; tw2.w = w4[2].w + Fv2.w;
            tw3.x = w4[3].x + Fv3.x; tw3.y = w4[3].y + Fv3.y; tw3.z = w4[3].z + Fv3.z; tw3.w = w4[3].w + Fv3.w;

            float tot = warp_sum(dxp[u] + d4(ha, tw2) + d4(hb, tw3));
            const float rr = rn[u];
            const float hn = tanh_fast(tot + bia) * rr;

            const float4* __restrict__ xr = (const float4*)(x + ((size_t)bi * Tn + t) * In);
            float4 xv0 = __ldg(xr + lane);        // L1 hit (touched last step)
            float4 xv1 = __ldg(xr + 32 + lane);
            float4 Fv0 = Fr[lane], Fv1 = Fr[32 + lane];

            float4 n0, n1, n2, n3;
            n0.x = l4[0].x * (Fv0.x * rr) + g4[0].x * (xv0.x * hn);
            n0.y = l4[0].y * (Fv0.y * rr) + g4[0].y * (xv0.y * hn);
            n0.z = l4[0].z * (Fv0.z * rr) + g4[0].z * (xv0.z * hn);
            n0.w = l4[0].w * (Fv0.w * rr) + g4[0].w * (xv0.w * hn);
            n1.x = l4[1].x * (Fv1.x * rr) + g4[1].x * (xv1.x * hn);
            n1.y = l4[1].y * (Fv1.y * rr) + g4[1].y * (xv1.y * hn);
            n1.z = l4[1].z * (Fv1.z * rr) + g4[1].z * (xv1.z * hn);
            n1.w = l4[1].w * (Fv1.w * rr) + g4[1].w * (xv1.w * hn);
            n2.x = l4[2].x * (Fv2.x * rr) + g4[2].x * (ha.x * hn);
            n2.y = l4[2].y * (Fv2.y * rr) + g4[2].y * (ha.y * hn);
            n2.z = l4[2].z * (Fv2.z * rr) + g4[2].z * (ha.z * hn);
            n2.w = l4[2].w * (Fv2.w * rr) + g4[2].w * (ha.w * hn);
            n3.x = l4[3].x * (Fv3.x * rr) + g4[3].x * (hb.x * hn);
            n3.y = l4[3].y * (Fv3.y * rr) + g4[3].y * (hb.y * hn);
            n3.z = l4[3].z * (Fv3.z * rr) + g4[3].z * (hb.z * hn);
            n3.w = l4[3].w * (Fv3.w * rr) + g4[3].w * (hb.w * hn);
            Fr[lane] = n0;
            Fr[32 + lane] = n1;
            Fr[64 + lane] = n2;
            Fr[96 + lane] = n3;

            // next-step partials from registers (tw_next = W + F_new)
            float4 t0, t1, t2, t3;
            t0.x = w4[0].x + n0.x; t0.y = w4[0].y + n0.y; t0.z = w4[0].z + n0.z; t0.w = w4[0].w + n0.w;
            t1.x = w4[1].x + n1.x; t1.y = w4[1].y + n1.y; t1.z = w4[1].z + n1.z; t1.w = w4[1].w + n1.w;
            t2.x = w4[2].x + n2.x; t2.y = w4[2].y + n2.y; t2.z = w4[2].z + n2.z; t2.w = w4[2].w + n2.w;
            t3.x = w4[3].x + n3.x; t3.y = w4[3].y + n3.y; t3.z = w4[3].z + n3.z; t3.w = w4[3].w + n3.w;
            ssp[u] = d4(t0, t0) + d4(t1, t1) + d4(t2, t2) + d4(t3, t3);

            const float4* __restrict__ xq = (const float4*)(x + ((size_t)bi * Tn + tn) * In);
            float4 xa = __ldg(xq + lane);
            float4 xb = __ldg(xq + 32 + lane);
            dxp[u] = d4(xa, t0) + d4(xb, t1);

            if (lane == 0) hout[bi * Hn + h] = hn;
            ha = han; hb = hbn;
        }

        // ---------- arrive ----------
        __syncthreads();
        if (tid == 0) red_release(&g_bar);
    }

    // ---- F writeout (warp-private rows) ----
    float* __restrict__ Fout = out + Bn * On + Bn * Hn;
    float4* __restrict__ Fo4 = (float4*)Fout;
#pragma unroll
    for (int u = 0; u < 4; u++) {
        const int bb = bi0 + u * 8;
        const int grow = bb * Hn + h;
        const float4* Fr = F4 + bb * (IH / 4);
#pragma unroll
        for (int k = 0; k < 4; k++) {
            int f4 = k * 32 + lane;
            Fo4[(size_t)grow * (IH / 4) + f4] = Fr[f4];
        }
    }

    // ---- epilogue: needs all blocks' final h ----
    if (blockIdx.x < 64) {
        if (tid == 0) {
            const unsigned target = (unsigned)NBLK * (unsigned)Tn;
            while (ld_acquire(&g_bar) < target) __nanosleep(32);
        }
        __syncthreads();
    }

    if (blockIdx.x < 32) {
        const int b = blockIdx.x;
        for (int i = tid; i < Hn; i += NTHR)
            F_sm[i] = __ldcg(&g_h[0][b * Hn + i]);   // T even -> final h in buf 0
        __syncthreads();
        const float4* hv4 = (const float4*)F_sm;
        for (int o = wid; o < On; o += 8) {
            const float4* wr = (const float4*)(Wout + (size_t)o * Hn);
            float acc = 0.f;
#pragma unroll
            for (int k = 0; k < 2; k++) {
                int j4 = k * 32 + lane;
                acc += d4(__ldg(wr + j4), hv4[j4]);
            }
            acc = warp_sum(acc);
            if (lane == 0) out[b * On + o] = acc + __ldg(bout + o);
        }
    } else if (blockIdx.x < 64) {
        const int b = blockIdx.x - 32;
        for (int i = tid; i < Hn; i += NTHR)
            out[Bn * On + b * Hn + i] = __ldcg(&g_h[0][b * Hn + i]);
    }
}

// ---------------------------------------------------------------------------
extern "C" void kernel_launch(void* const* d_in, const int* in_sizes, int n_in,
                              void* d_out, int out_size)
{
    const float* sentence = (const float*)d_in[0];
    const float* Wl   = (const float*)d_in[1];
    const float* Wg   = (const float*)d_in[2];
    const float* W    = (const float*)d_in[3];
    const float* bias = (const float*)d_in[4];
    const float* Wout = (const float*)d_in[5];
    const float* bout = (const float*)d_in[6];
    float* out = (float*)d_out;

    const int smem = 32 * IH * sizeof(float);  // 65536
    cudaFuncSetAttribute(persist_kernel, cudaFuncAttributeMaxDynamicSharedMemorySize, smem);

    init_kernel<<<32, 256>>>();
    persist_kernel<<<NBLK, NTHR, smem>>>(sentence, Wl, Wg, W, bias, Wout, bout, out);
}

// round 7
// speedup vs baseline: 1.1884x; 1.1884x over previous
#include <cuda_runtime.h>

#define Bn 32
#define Tn 128
#define In 256
#define Hn 256
#define IH 512
#define On 128
#define NBLK 256      // persistent blocks; 64 KB smem, <=128 regs => 2 blocks/SM
#define NTHR 256      // 8 warps

__device__ float g_h[2][Bn * Hn];   // ping-pong hidden state
__device__ unsigned g_bar;          // monotonic grid-barrier counter (1 inc/block/step)

// ---------------------------------------------------------------------------
__global__ void init_kernel()
{
    int i = blockIdx.x * blockDim.x + threadIdx.x;
    if (i == 0) g_bar = 0u;
    for (int k = i; k < Bn * Hn; k += gridDim.x * blockDim.x) g_h[0][k] = 0.f;
}

// ---------------------------------------------------------------------------
__device__ __forceinline__ float warp_sum(float v)
{
#pragma unroll
    for (int o = 16; o > 0; o >>= 1) v += __shfl_xor_sync(0xffffffffu, v, o);
    return v;
}
__device__ __forceinline__ float tanh_fast(float v)
{
    float r; asm("tanh.approx.f32 %0, %1;" : "=f"(r) : "f"(v)); return r;
}
__device__ __forceinline__ unsigned ld_acquire(const unsigned* p)
{
    unsigned v;
    asm volatile("ld.acquire.gpu.global.u32 %0, [%1];" : "=r"(v) : "l"(p) : "memory");
    return v;
}
__device__ __forceinline__ void red_release(unsigned* p)
{
    asm volatile("red.release.gpu.global.add.u32 [%0], 1;" :: "l"(p) : "memory");
}
// smem arrive: acq_rel, cta scope; returns old value.
__device__ __forceinline__ unsigned atom_inc_cta_shared(unsigned* p)
{
    unsigned old;
    unsigned addr = (unsigned)__cvta_generic_to_shared(p);
    asm volatile("atom.acq_rel.cta.shared.add.u32 %0, [%1], 1;"
                 : "=r"(old) : "r"(addr) : "memory");
    return old;
}
__device__ __forceinline__ float d4(float4 a, float4 b)
{
    return a.x * b.x + a.y * b.y + a.z * b.z + a.w * b.w;
}

// ---------------------------------------------------------------------------
// Persistent kernel, 2 blocks/SM. Block owns h-row bid x 32 batches; F slice
// (32 rows x 512 = 64 KB) in smem. Warp w handles batches w + {0,8,16,24}.
// Lane f-slice: float4 idx k*32+lane, k=0..3.
//
// Step = [reduce ss->rn | wait | B1: dots+tanh+h-store | ARRIVE | B2: F
// writeback + fused next-step partials]. Only B1 is on the global critical
// path; B2 and the reduce overlap other blocks' B1/wait.
// ---------------------------------------------------------------------------
__global__ __launch_bounds__(NTHR, 2) void persist_kernel(
    const float* __restrict__ x,
    const float* __restrict__ Wl,
    const float* __restrict__ Wg,
    const float* __restrict__ W,
    const float* __restrict__ bias,
    const float* __restrict__ Wout,
    const float* __restrict__ bout,
    float* __restrict__ out)
{
    extern __shared__ float F_sm[];            // 32 * 512 floats = 64 KB
    float4* __restrict__ F4 = (float4*)F_sm;   // [32][128]
    __shared__ unsigned s_cnt;                 // per-block arrival counter

    const int tid  = threadIdx.x;
    const int wid  = tid >> 5, lane = tid & 31;
    const int bi0  = wid;                      // 0..7
    const int h    = blockIdx.x;

    if (tid == 0) s_cnt = 0u;

    // Pin this block's weight-row slices in registers.
    float4 w4[4], l4[4], g4[4];
    {
        const float4* Wp = (const float4*)(W  + (size_t)h * IH);
        const float4* Lp = (const float4*)(Wl + (size_t)h * IH);
        const float4* Gp = (const float4*)(Wg + (size_t)h * IH);
#pragma unroll
        for (int k = 0; k < 4; k++) {
            int f4 = k * 32 + lane;
            w4[k] = __ldg(Wp + f4);
            l4[k] = __ldg(Lp + f4);
            g4[k] = __ldg(Gp + f4);
        }
    }
    const float bia = __ldg(bias + h);

    // Zero this warp's F rows (warp-private).
    {
        float4 z = make_float4(0.f, 0.f, 0.f, 0.f);
#pragma unroll
        for (int u = 0; u < 4; u++) {
            float4* Fr = F4 + (bi0 + u * 8) * (IH / 4);
#pragma unroll
            for (int k = 0; k < 4; k++) Fr[k * 32 + lane] = z;
        }
    }

    // Bootstrap partials for t=0 (F=0 => tw=W).
    float ssp[4], dxp[4], rn[4], hn[4];
    {
        const float ssw = d4(w4[0], w4[0]) + d4(w4[1], w4[1])
                        + d4(w4[2], w4[2]) + d4(w4[3], w4[3]);
#pragma unroll
        for (int u = 0; u < 4; u++) {
            const int bi = bi0 + u * 8;
            const float4* xr = (const float4*)(x + (size_t)bi * Tn * In);
            float4 xv0 = __ldg(xr + lane);
            float4 xv1 = __ldg(xr + 32 + lane);
            ssp[u] = ssw;
            dxp[u] = d4(xv0, w4[0]) + d4(xv1, w4[1]);
        }
    }

    for (int t = 0; t < Tn; t++) {
        const float4* __restrict__ hin = (const float4*)g_h[t & 1];
        float* __restrict__ hout = g_h[(t & 1) ^ 1];
        const int tn = (t + 1 < Tn) ? t + 1 : t;   // clamped next-x index

        // ss reduce + rsqrt (off critical path; 4 interleaved chains).
#pragma unroll
        for (int o = 16; o > 0; o >>= 1) {
            ssp[0] += __shfl_xor_sync(0xffffffffu, ssp[0], o);
            ssp[1] += __shfl_xor_sync(0xffffffffu, ssp[1], o);
            ssp[2] += __shfl_xor_sync(0xffffffffu, ssp[2], o);
            ssp[3] += __shfl_xor_sync(0xffffffffu, ssp[3], o);
        }
#pragma unroll
        for (int u = 0; u < 4; u++) rn[u] = rsqrtf(ssp[u]);

        // ---------- wait: h(t-1) published by all blocks ----------
        if (tid == 0) {
            const unsigned target = (unsigned)NBLK * (unsigned)t;
            while (ld_acquire(&g_bar) < target) __nanosleep(32);
        }
        __syncthreads();

        // ---------- B1 (critical span): dots -> h_new -> publish ----------
        float4 ha[4], hb[4];
#pragma unroll
        for (int u = 0; u < 4; u++) {          // 8 LDGs issued up front (MLP)
            const int bi = bi0 + u * 8;
            ha[u] = __ldcg(hin + bi * (Hn / 4) + lane);
            hb[u] = __ldcg(hin + bi * (Hn / 4) + 32 + lane);
        }
#pragma unroll
        for (int u = 0; u < 4; u++) {
            const int bi = bi0 + u * 8;
            const float4* __restrict__ Fr = F4 + bi * (IH / 4);
            float4 Fv2 = Fr[64 + lane], Fv3 = Fr[96 + lane];
            float4 tw2, tw3;
            tw2.x = w4[2].x + Fv2.x; tw2.y = w4[2].y + Fv2.y; tw2.z = w4[2].z + Fv2.z; tw2.w = w4[2].w + Fv2.w;
            tw3.x = w4[3].x + Fv3.x; tw3.y = w4[3].y + Fv3.y; tw3.z = w4[3].z + Fv3.z; tw3.w = w4[3].w + Fv3.w;
            float tot = warp_sum(dxp[u] + d4(ha[u], tw2) + d4(hb[u], tw3));
            hn[u] = tanh_fast(tot + bia) * rn[u];
            if (lane == 0) hout[bi * Hn + h] = hn[u];
        }

        // ---------- ARRIVE (hierarchical: smem acq_rel -> 1 global red) ----------
        if (lane == 0) {
            unsigned old = atom_inc_cta_shared(&s_cnt);
            if ((old & 7u) == 7u) red_release(&g_bar);
        }

        // ---------- B2 (off critical path): writeback + next partials ----------
#pragma unroll
        for (int u = 0; u < 4; u++) {
            const int bi = bi0 + u * 8;
            float4* __restrict__ Fr = F4 + bi * (IH / 4);
            const float rr = rn[u];
            const float hv = hn[u];

            const float4* __restrict__ xr = (const float4*)(x + ((size_t)bi * Tn + t) * In);
            float4 xv0 = __ldg(xr + lane);          // L1 hits (loaded last step)
            float4 xv1 = __ldg(xr + 32 + lane);
            float4 Fv0 = Fr[lane], Fv1 = Fr[32 + lane];
            float4 Fv2 = Fr[64 + lane], Fv3 = Fr[96 + lane];

            float4 n0, n1, n2, n3;
            n0.x = l4[0].x * (Fv0.x * rr) + g4[0].x * (xv0.x * hv);
            n0.y = l4[0].y * (Fv0.y * rr) + g4[0].y * (xv0.y * hv);
            n0.z = l4[0].z * (Fv0.z * rr) + g4[0].z * (xv0.z * hv);
            n0.w = l4[0].w * (Fv0.w * rr) + g4[0].w * (xv0.w * hv);
            n1.x = l4[1].x * (Fv1.x * rr) + g4[1].x * (xv1.x * hv);
            n1.y = l4[1].y * (Fv1.y * rr) + g4[1].y * (xv1.y * hv);
            n1.z = l4[1].z * (Fv1.z * rr) + g4[1].z * (xv1.z * hv);
            n1.w = l4[1].w * (Fv1.w * rr) + g4[1].w * (xv1.w * hv);
            n2.x = l4[2].x * (Fv2.x * rr) + g4[2].x * (ha[u].x * hv);
            n2.y = l4[2].y * (Fv2.y * rr) + g4[2].y * (ha[u].y * hv);
            n2.z = l4[2].z * (Fv2.z * rr) + g4[2].z * (ha[u].z * hv);
            n2.w = l4[2].w * (Fv2.w * rr) + g4[2].w * (ha[u].w * hv);
            n3.x = l4[3].x * (Fv3.x * rr) + g4[3].x * (hb[u].x * hv);
            n3.y = l4[3].y * (Fv3.y * rr) + g4[3].y * (hb[u].y * hv);
            n3.z = l4[3].z * (Fv3.z * rr) + g4[3].z * (hb[u].z * hv);
            n3.w = l4[3].w * (Fv3.w * rr) + g4[3].w * (hb[u].w * hv);
            Fr[lane] = n0;
            Fr[32 + lane] = n1;
            Fr[64 + lane] = n2;
            Fr[96 + lane] = n3;

            // next-step partials from registers (tw_next = W + F_new)
            float4 t0, t1, t2, t3;
            t0.x = w4[0].x + n0.x; t0.y = w4[0].y + n0.y; t0.z = w4[0].z + n0.z; t0.w = w4[0].w + n0.w;
            t1.x = w4[1].x + n1.x; t1.y = w4[1].y + n1.y; t1.z = w4[1].z + n1.z; t1.w = w4[1].w + n1.w;
            t2.x = w4[2].x + n2.x; t2.y = w4[2].y + n2.y; t2.z = w4[2].z + n2.z; t2.w = w4[2].w + n2.w;
            t3.x = w4[3].x + n3.x; t3.y = w4[3].y + n3.y; t3.z = w4[3].z + n3.z; t3.w = w4[3].w + n3.w;
            ssp[u] = d4(t0, t0) + d4(t1, t1) + d4(t2, t2) + d4(t3, t3);

            const float4* __restrict__ xq = (const float4*)(x + ((size_t)bi * Tn + tn) * In);
            float4 xa = __ldg(xq + lane);
            float4 xb = __ldg(xq + 32 + lane);
            dxp[u] = d4(xa, t0) + d4(xb, t1);
        }
    }

    // ---- F writeout (warp-private rows) ----
    float* __restrict__ Fout = out + Bn * On + Bn * Hn;
    float4* __restrict__ Fo4 = (float4*)Fout;
#pragma unroll
    for (int u = 0; u < 4; u++) {
        const int bb = bi0 + u * 8;
        const int grow = bb * Hn + h;
        const float4* Fr = F4 + bb * (IH / 4);
#pragma unroll
        for (int k = 0; k < 4; k++) {
            int f4 = k * 32 + lane;
            Fo4[(size_t)grow * (IH / 4) + f4] = Fr[f4];
        }
    }

    // ---- epilogue: needs all blocks' final h ----
    if (blockIdx.x < 64) {
        if (tid == 0) {
            const unsigned target = (unsigned)NBLK * (unsigned)Tn;
            while (ld_acquire(&g_bar) < target) __nanosleep(32);
        }
        __syncthreads();
    }

    if (blockIdx.x < 32) {
        const int b = blockIdx.x;
        for (int i = tid; i < Hn; i += NTHR)
            F_sm[i] = __ldcg(&g_h[0][b * Hn + i]);   // T even -> final h in buf 0
        __syncthreads();
        const float4* hv4 = (const float4*)F_sm;
        for (int o = wid; o < On; o += 8) {
            const float4* wr = (const float4*)(Wout + (size_t)o * Hn);
            float acc = 0.f;
#pragma unroll
            for (int k = 0; k < 2; k++) {
                int j4 = k * 32 + lane;
                acc += d4(__ldg(wr + j4), hv4[j4]);
            }
            acc = warp_sum(acc);
            if (lane == 0) out[b * On + o] = acc + __ldg(bout + o);
        }
    } else if (blockIdx.x < 64) {
        const int b = blockIdx.x - 32;
        for (int i = tid; i < Hn; i += NTHR)
            out[Bn * On + b * Hn + i] = __ldcg(&g_h[0][b * Hn + i]);
    }
}

// ---------------------------------------------------------------------------
extern "C" void kernel_launch(void* const* d_in, const int* in_sizes, int n_in,
                              void* d_out, int out_size)
{
    const float* sentence = (const float*)d_in[0];
    const float* Wl   = (const float*)d_in[1];
    const float* Wg   = (const float*)d_in[2];
    const float* W    = (const float*)d_in[3];
    const float* bias = (const float*)d_in[4];
    const float* Wout = (const float*)d_in[5];
    const float* bout = (const float*)d_in[6];
    float* out = (float*)d_out;

    const int smem = 32 * IH * sizeof(float);  // 65536
    cudaFuncSetAttribute(persist_kernel, cudaFuncAttributeMaxDynamicSharedMemorySize, smem);

    init_kernel<<<32, 256>>>();
    persist_kernel<<<NBLK, NTHR, smem>>>(sentence, Wl, Wg, W, bias, Wout, bout, out);
}

// round 8
// speedup vs baseline: 1.2403x; 1.0436x over previous
#include <cuda_runtime.h>

#define Bn 32
#define Tn 128
#define In 256
#define Hn 256
#define IH 512
#define On 128
#define NBLK 256      // persistent blocks; 64 KB smem, <=128 regs => 2 blocks/SM
#define NTHR 256      // 8 warps

typedef unsigned long long ull;

__device__ float g_h[2][Bn * Hn];   // ping-pong hidden state
__device__ unsigned g_bar;          // monotonic grid-barrier counter (1 inc/block/step)

// ---------------------------------------------------------------------------
__global__ void init_kernel()
{
    int i = blockIdx.x * blockDim.x + threadIdx.x;
    if (i == 0) g_bar = 0u;
    for (int k = i; k < Bn * Hn; k += gridDim.x * blockDim.x) g_h[0][k] = 0.f;
}

// ---------------------------------------------------------------------------
__device__ __forceinline__ float warp_sum(float v)
{
#pragma unroll
    for (int o = 16; o > 0; o >>= 1) v += __shfl_xor_sync(0xffffffffu, v, o);
    return v;
}
__device__ __forceinline__ float tanh_fast(float v)
{
    float r; asm("tanh.approx.f32 %0, %1;" : "=f"(r) : "f"(v)); return r;
}
__device__ __forceinline__ unsigned ld_acquire(const unsigned* p)
{
    unsigned v;
    asm volatile("ld.acquire.gpu.global.u32 %0, [%1];" : "=r"(v) : "l"(p) : "memory");
    return v;
}
__device__ __forceinline__ void red_release(unsigned* p)
{
    asm volatile("red.release.gpu.global.add.u32 [%0], 1;" :: "l"(p) : "memory");
}
__device__ __forceinline__ unsigned atom_inc_cta_shared(unsigned* p)
{
    unsigned old;
    unsigned addr = (unsigned)__cvta_generic_to_shared(p);
    asm volatile("atom.acq_rel.cta.shared.add.u32 %0, [%1], 1;"
                 : "=r"(old) : "r"(addr) : "memory");
    return old;
}
// ---- packed f32x2 primitives (Blackwell FFMA2 path; PTX-only) ----
__device__ __forceinline__ ull f2_add(ull a, ull b)
{ ull d; asm("add.rn.f32x2 %0, %1, %2;" : "=l"(d) : "l"(a), "l"(b)); return d; }
__device__ __forceinline__ ull f2_mul(ull a, ull b)
{ ull d; asm("mul.rn.f32x2 %0, %1, %2;" : "=l"(d) : "l"(a), "l"(b)); return d; }
__device__ __forceinline__ ull f2_fma(ull a, ull b, ull c)
{ ull d; asm("fma.rn.f32x2 %0, %1, %2, %3;" : "=l"(d) : "l"(a), "l"(b), "l"(c)); return d; }
__device__ __forceinline__ ull f2_bcast(float v)
{ ull d; asm("mov.b64 %0, {%1, %1};" : "=l"(d) : "f"(v)); return d; }
__device__ __forceinline__ float f2_fold(ull v)
{ float lo, hi; asm("mov.b64 {%0, %1}, %2;" : "=f"(lo), "=f"(hi) : "l"(v)); return lo + hi; }
// 16B vector loads in the pair domain
__device__ __forceinline__ ulonglong2 ldnc2(const ulonglong2* p)
{ ulonglong2 v; asm("ld.global.nc.v2.u64 {%0,%1}, [%2];" : "=l"(v.x), "=l"(v.y) : "l"(p)); return v; }
__device__ __forceinline__ ulonglong2 ldcg2(const ulonglong2* p)
{ ulonglong2 v; asm volatile("ld.global.cg.v2.u64 {%0,%1}, [%2];" : "=l"(v.x), "=l"(v.y) : "l"(p)); return v; }

// ---------------------------------------------------------------------------
// Persistent kernel, 2 blocks/SM. Block owns h-row bid x 32 batches; F slice
// (32 rows x 512 = 64 KB) in smem, viewed as ulonglong2 (f32x2 pairs).
// Warp w handles batches w + {0,8,16,24}; lane slice: idx k*32+lane, k=0..3
// in 16-byte units (one ulonglong2 = 2 f32x2 pairs = float4).
//
// Step = [pair-domain ss reduce | wait | B1: dots+tanh+h-store | ARRIVE |
// B2: writeback + fused next-step partials]. All arithmetic uses f32x2.
// ---------------------------------------------------------------------------
__global__ __launch_bounds__(NTHR, 2) void persist_kernel(
    const float* __restrict__ x,
    const float* __restrict__ Wl,
    const float* __restrict__ Wg,
    const float* __restrict__ W,
    const float* __restrict__ bias,
    const float* __restrict__ Wout,
    const float* __restrict__ bout,
    float* __restrict__ out)
{
    extern __shared__ float F_sm[];                    // 64 KB
    ulonglong2* __restrict__ F2 = (ulonglong2*)F_sm;   // [32][128] 16B units
    __shared__ unsigned s_cnt;

    const int tid  = threadIdx.x;
    const int wid  = tid >> 5, lane = tid & 31;
    const int bi0  = wid;                      // 0..7
    const int h    = blockIdx.x;

    if (tid == 0) s_cnt = 0u;

    // Pin this block's weight-row slices (pair domain).
    ulonglong2 w2[4], l2[4], g2[4];
    {
        const ulonglong2* Wp = (const ulonglong2*)(W  + (size_t)h * IH);
        const ulonglong2* Lp = (const ulonglong2*)(Wl + (size_t)h * IH);
        const ulonglong2* Gp = (const ulonglong2*)(Wg + (size_t)h * IH);
#pragma unroll
        for (int k = 0; k < 4; k++) {
            int f4 = k * 32 + lane;
            w2[k] = ldnc2(Wp + f4);
            l2[k] = ldnc2(Lp + f4);
            g2[k] = ldnc2(Gp + f4);
        }
    }
    const float bia = __ldg(bias + h);

    // Zero this warp's F rows.
    {
        ulonglong2 z; z.x = 0ull; z.y = 0ull;
#pragma unroll
        for (int u = 0; u < 4; u++) {
            ulonglong2* Fr = F2 + (bi0 + u * 8) * (IH / 4);
#pragma unroll
            for (int k = 0; k < 4; k++) Fr[k * 32 + lane] = z;
        }
    }

    // Bootstrap partials for t=0 (F=0 => tw=W).
    float ssp[4], rn[4], hn[4];
    ull dxp[4];
    {
        ull sw = f2_mul(w2[0].x, w2[0].x);
        sw = f2_fma(w2[0].y, w2[0].y, sw);
        sw = f2_fma(w2[1].x, w2[1].x, sw);
        sw = f2_fma(w2[1].y, w2[1].y, sw);
        sw = f2_fma(w2[2].x, w2[2].x, sw);
        sw = f2_fma(w2[2].y, w2[2].y, sw);
        sw = f2_fma(w2[3].x, w2[3].x, sw);
        sw = f2_fma(w2[3].y, w2[3].y, sw);
        const float ssw = f2_fold(sw);
#pragma unroll
        for (int u = 0; u < 4; u++) {
            const int bi = bi0 + u * 8;
            const ulonglong2* xr = (const ulonglong2*)(x + (size_t)bi * Tn * In);
            ulonglong2 xv0 = ldnc2(xr + lane);
            ulonglong2 xv1 = ldnc2(xr + 32 + lane);
            ull a = f2_mul(xv0.x, w2[0].x);
            a = f2_fma(xv0.y, w2[0].y, a);
            a = f2_fma(xv1.x, w2[1].x, a);
            a = f2_fma(xv1.y, w2[1].y, a);
            ssp[u] = ssw;
            dxp[u] = a;
        }
    }

    for (int t = 0; t < Tn; t++) {
        const ulonglong2* __restrict__ hin = (const ulonglong2*)g_h[t & 1];
        float* __restrict__ hout = g_h[(t & 1) ^ 1];
        const int tn = (t + 1 < Tn) ? t + 1 : t;

        // ss reduce + rsqrt (off critical path; 4 interleaved chains).
#pragma unroll
        for (int o = 16; o > 0; o >>= 1) {
            ssp[0] += __shfl_xor_sync(0xffffffffu, ssp[0], o);
            ssp[1] += __shfl_xor_sync(0xffffffffu, ssp[1], o);
            ssp[2] += __shfl_xor_sync(0xffffffffu, ssp[2], o);
            ssp[3] += __shfl_xor_sync(0xffffffffu, ssp[3], o);
        }
#pragma unroll
        for (int u = 0; u < 4; u++) rn[u] = rsqrtf(ssp[u]);

        // ---------- wait: h(t-1) published by all blocks ----------
        if (tid == 0) {
            const unsigned target = (unsigned)NBLK * (unsigned)t;
            while (ld_acquire(&g_bar) < target) __nanosleep(32);
        }
        __syncthreads();

        // ---------- B1 (critical span): dots -> h_new -> publish ----------
        ulonglong2 ha[4], hb[4];
#pragma unroll
        for (int u = 0; u < 4; u++) {          // 8 LDGs up front (MLP)
            const int bi = bi0 + u * 8;
            ha[u] = ldcg2(hin + bi * (Hn / 16) * 4 + lane);      // Hn floats = 64 u2
            hb[u] = ldcg2(hin + bi * (Hn / 16) * 4 + 32 + lane);
        }
#pragma unroll
        for (int u = 0; u < 4; u++) {
            const int bi = bi0 + u * 8;
            const ulonglong2* __restrict__ Fr = F2 + bi * (IH / 4);
            ulonglong2 Fv2 = Fr[64 + lane], Fv3 = Fr[96 + lane];
            ull t2x = f2_add(w2[2].x, Fv2.x), t2y = f2_add(w2[2].y, Fv2.y);
            ull t3x = f2_add(w2[3].x, Fv3.x), t3y = f2_add(w2[3].y, Fv3.y);
            ull acc = dxp[u];
            acc = f2_fma(ha[u].x, t2x, acc);
            acc = f2_fma(ha[u].y, t2y, acc);
            acc = f2_fma(hb[u].x, t3x, acc);
            acc = f2_fma(hb[u].y, t3y, acc);
            float tot = warp_sum(f2_fold(acc));
            hn[u] = tanh_fast(tot + bia) * rn[u];
            if (lane == 0) hout[bi * Hn + h] = hn[u];
        }

        // ---------- ARRIVE (hierarchical: smem acq_rel -> 1 global red) ----------
        if (lane == 0) {
            unsigned old = atom_inc_cta_shared(&s_cnt);
            if ((old & 7u) == 7u) red_release(&g_bar);
        }

        // ---------- B2 (off critical path): writeback + next partials ----------
#pragma unroll
        for (int u = 0; u < 4; u++) {
            const int bi = bi0 + u * 8;
            ulonglong2* __restrict__ Fr = F2 + bi * (IH / 4);
            const ull rr2 = f2_bcast(rn[u]);
            const ull hv2 = f2_bcast(hn[u]);

            const ulonglong2* __restrict__ xr =
                (const ulonglong2*)(x + ((size_t)bi * Tn + t) * In);
            ulonglong2 xv0 = ldnc2(xr + lane);          // L1 hits
            ulonglong2 xv1 = ldnc2(xr + 32 + lane);
            ulonglong2 Fv0 = Fr[lane],      Fv1 = Fr[32 + lane];
            ulonglong2 Fv2 = Fr[64 + lane], Fv3 = Fr[96 + lane];

            // n = l*(F*rr) + g*(in*hv)   (4 f32x2 ops per pair)
            ulonglong2 n0, n1, n2, n3;
            n0.x = f2_fma(g2[0].x, f2_mul(xv0.x, hv2), f2_mul(l2[0].x, f2_mul(Fv0.x, rr2)));
            n0.y = f2_fma(g2[0].y, f2_mul(xv0.y, hv2), f2_mul(l2[0].y, f2_mul(Fv0.y, rr2)));
            n1.x = f2_fma(g2[1].x, f2_mul(xv1.x, hv2), f2_mul(l2[1].x, f2_mul(Fv1.x, rr2)));
            n1.y = f2_fma(g2[1].y, f2_mul(xv1.y, hv2), f2_mul(l2[1].y, f2_mul(Fv1.y, rr2)));
            n2.x = f2_fma(g2[2].x, f2_mul(ha[u].x, hv2), f2_mul(l2[2].x, f2_mul(Fv2.x, rr2)));
            n2.y = f2_fma(g2[2].y, f2_mul(ha[u].y, hv2), f2_mul(l2[2].y, f2_mul(Fv2.y, rr2)));
            n3.x = f2_fma(g2[3].x, f2_mul(hb[u].x, hv2), f2_mul(l2[3].x, f2_mul(Fv3.x, rr2)));
            n3.y = f2_fma(g2[3].y, f2_mul(hb[u].y, hv2), f2_mul(l2[3].y, f2_mul(Fv3.y, rr2)));
            Fr[lane] = n0;
            Fr[32 + lane] = n1;
            Fr[64 + lane] = n2;
            Fr[96 + lane] = n3;

            // tw_next = W + F_new; ss and dx partials in pair domain
            ull t0x = f2_add(w2[0].x, n0.x), t0y = f2_add(w2[0].y, n0.y);
            ull t1x = f2_add(w2[1].x, n1.x), t1y = f2_add(w2[1].y, n1.y);
            ull t2x = f2_add(w2[2].x, n2.x), t2y = f2_add(w2[2].y, n2.y);
            ull t3x = f2_add(w2[3].x, n3.x), t3y = f2_add(w2[3].y, n3.y);

            ull ss = f2_mul(t0x, t0x);
            ss = f2_fma(t0y, t0y, ss);
            ss = f2_fma(t1x, t1x, ss);
            ss = f2_fma(t1y, t1y, ss);
            ss = f2_fma(t2x, t2x, ss);
            ss = f2_fma(t2y, t2y, ss);
            ss = f2_fma(t3x, t3x, ss);
            ss = f2_fma(t3y, t3y, ss);
            ssp[u] = f2_fold(ss);

            const ulonglong2* __restrict__ xq =
                (const ulonglong2*)(x + ((size_t)bi * Tn + tn) * In);
            ulonglong2 xa = ldnc2(xq + lane);
            ulonglong2 xb = ldnc2(xq + 32 + lane);
            ull dx = f2_mul(xa.x, t0x);
            dx = f2_fma(xa.y, t0y, dx);
            dx = f2_fma(xb.x, t1x, dx);
            dx = f2_fma(xb.y, t1y, dx);
            dxp[u] = dx;
        }
    }

    // ---- F writeout (warp-private rows) ----
    float* __restrict__ Fout = out + Bn * On + Bn * Hn;
    ulonglong2* __restrict__ Fo2 = (ulonglong2*)Fout;
#pragma unroll
    for (int u = 0; u < 4; u++) {
        const int bb = bi0 + u * 8;
        const int grow = bb * Hn + h;
        const ulonglong2* Fr = F2 + bb * (IH / 4);
#pragma unroll
        for (int k = 0; k < 4; k++) {
            int f4 = k * 32 + lane;
            Fo2[(size_t)grow * (IH / 4) + f4] = Fr[f4];
        }
    }

    // ---- epilogue: needs all blocks' final h ----
    if (blockIdx.x < 64) {
        if (tid == 0) {
            const unsigned target = (unsigned)NBLK * (unsigned)Tn;
            while (ld_acquire(&g_bar) < target) __nanosleep(32);
        }
        __syncthreads();
    }

    if (blockIdx.x < 32) {
        const int b = blockIdx.x;
        for (int i = tid; i < Hn; i += NTHR)
            F_sm[i] = __ldcg(&g_h[0][b * Hn + i]);   // T even -> final h in buf 0
        __syncthreads();
        const float4* hv4 = (const float4*)F_sm;
        for (int o = wid; o < On; o += 8) {
            const float4* wr = (const float4*)(Wout + (size_t)o * Hn);
            float acc = 0.f;
#pragma unroll
            for (int k = 0; k < 2; k++) {
                int j4 = k * 32 + lane;
                float4 w = __ldg(wr + j4);
                float4 hv = hv4[j4];
                acc += w.x * hv.x + w.y * hv.y + w.z * hv.z + w.w * hv.w;
            }
            acc = warp_sum(acc);
            if (lane == 0) out[b * On + o] = acc + __ldg(bout + o);
        }
    } else if (blockIdx.x < 64) {
        const int b = blockIdx.x - 32;
        for (int i = tid; i < Hn; i += NTHR)
            out[Bn * On + b * Hn + i] = __ldcg(&g_h[0][b * Hn + i]);
    }
}

// ---------------------------------------------------------------------------
extern "C" void kernel_launch(void* const* d_in, const int* in_sizes, int n_in,
                              void* d_out, int out_size)
{
    const float* sentence = (const float*)d_in[0];
    const float* Wl   = (const float*)d_in[1];
    const float* Wg   = (const float*)d_in[2];
    const float* W    = (const float*)d_in[3];
    const float* bias = (const float*)d_in[4];
    const float* Wout = (const float*)d_in[5];
    const float* bout = (const float*)d_in[6];
    float* out = (float*)d_out;

    const int smem = 32 * IH * sizeof(float);  // 65536
    cudaFuncSetAttribute(persist_kernel, cudaFuncAttributeMaxDynamicSharedMemorySize, smem);

    init_kernel<<<32, 256>>>();
    persist_kernel<<<NBLK, NTHR, smem>>>(sentence, Wl, Wg, W, bias, Wout, bout, out);
}